// round 3
// baseline (speedup 1.0000x reference)
#include <cuda_runtime.h>

#define HH 128           // hidden dim
#define AA 8             // heads
#define DD 16            // head dim
#define MAXN 50048
#define MAXE 800000
#define BM 64
#define BK 32
#define XS_STRIDE 68

// ---------------- device scratch (no allocations allowed) ----------------
__device__ __align__(128) float g_P[3][(size_t)MAXN * HH];   // projected Qn,Kn,Vn  (76.9 MB)
__device__ __align__(128) float g_WT[3][HH * HH];            // W transposed (k-major)
__device__ int g_count[MAXN];
__device__ int g_off[MAXN + 1];
__device__ int g_cursor[MAXN];
__device__ int g_eid[MAXE];

// ---------------- packed f32x2 helpers (Blackwell FFMA2) ----------------
__device__ __forceinline__ unsigned long long fma2(unsigned long long a,
                                                   unsigned long long b,
                                                   unsigned long long c) {
    unsigned long long d;
    asm("fma.rn.f32x2 %0, %1, %2, %3;" : "=l"(d) : "l"(a), "l"(b), "l"(c));
    return d;
}
__device__ __forceinline__ unsigned long long pack2(float lo, float hi) {
    unsigned long long d;
    asm("mov.b64 %0, {%1, %2};" : "=l"(d) : "f"(lo), "f"(hi));
    return d;
}
__device__ __forceinline__ float2 unpack2(unsigned long long v) {
    float2 r;
    asm("mov.b64 {%0, %1}, %2;" : "=f"(r.x), "=f"(r.y) : "l"(v));
    return r;
}

// ---------------- K0: transpose weights to k-major ----------------
__global__ void wt_kernel(const float* __restrict__ Wq,
                          const float* __restrict__ Wk,
                          const float* __restrict__ Wv) {
    int z = blockIdx.y;
    const float* W = (z == 0) ? Wq : (z == 1) ? Wk : Wv;
    int idx = blockIdx.x * 256 + threadIdx.x;
    if (idx < HH * HH) {
        int o = idx >> 7;
        int kk = idx & 127;
        g_WT[z][kk * HH + o] = W[idx];   // WT[k][o] = W[o][k]
    }
}

// ---------------- CSR build ----------------
__global__ void zero_kernel(int n) {
    int i = blockIdx.x * 256 + threadIdx.x;
    if (i < n) g_count[i] = 0;
}
__global__ void hist_kernel(const int* __restrict__ qi, int e) {
    int i = blockIdx.x * 256 + threadIdx.x;
    if (i < e) atomicAdd(&g_count[qi[i]], 1);
}
__global__ void scan_kernel(int n) {
    __shared__ int partial[1024];
    int t = threadIdx.x;
    int chunk = (n + 1023) / 1024;
    int start = t * chunk;
    int s = 0;
    for (int i = 0; i < chunk; i++) {
        int idx = start + i;
        if (idx < n) s += g_count[idx];
    }
    partial[t] = s;
    __syncthreads();
    for (int d = 1; d < 1024; d <<= 1) {
        int val = 0;
        if (t >= d) val = partial[t - d];
        __syncthreads();
        if (t >= d) partial[t] += val;
        __syncthreads();
    }
    int base = (t == 0) ? 0 : partial[t - 1];
    for (int i = 0; i < chunk; i++) {
        int idx = start + i;
        if (idx < n) {
            int c = g_count[idx];
            g_off[idx] = base;
            g_cursor[idx] = base;
            base += c;
        }
    }
    if (t == 1023) g_off[n] = partial[1023];
}
__global__ void scatter_kernel(const int* __restrict__ qi, int e) {
    int i = blockIdx.x * 256 + threadIdx.x;
    if (i < e) {
        int pos = atomicAdd(&g_cursor[qi[i]], 1);
        g_eid[pos] = i;
    }
}

// ---------------- K1: projection GEMM, Y = X @ W^T + b ----------------
// BM=64 rows x 128 cols per 256-thread block. Register tile 8x4 per thread,
// packed as 4x4 f32x2 accumulators (row pairs). W reads conflict-free
// (lane-consecutive 16B), X reads warp-broadcast from transposed smem tile.
__global__ void __launch_bounds__(256) proj_gemm(
    const float* __restrict__ Xq, const float* __restrict__ Xk,
    const float* __restrict__ Xv,
    const float* __restrict__ Bq, const float* __restrict__ Bk,
    const float* __restrict__ Bv, int M) {
    __shared__ __align__(16) float Ws[BK * HH];         // Ws[k][o]
    __shared__ __align__(16) float Xs[BK * XS_STRIDE];  // Xs[k][row], padded

    int z = blockIdx.z;
    const float* X = (z == 0) ? Xq : (z == 1) ? Xk : Xv;
    const float* B = (z == 0) ? Bq : (z == 1) ? Bk : Bv;
    const float* WT = g_WT[z];
    float* Y = g_P[z];

    int t = threadIdx.x;
    int m0 = blockIdx.x * BM;
    int tx = t & 31;
    int ty = t >> 5;
    int c0 = tx * 4;   // 4 output cols
    int r0 = ty * 8;   // 8 output rows

    unsigned long long acc[4][4];
#pragma unroll
    for (int p = 0; p < 4; p++)
#pragma unroll
        for (int c = 0; c < 4; c++) acc[p][c] = 0ull;

    for (int kt = 0; kt < HH; kt += BK) {
        __syncthreads();
        // W tile: straight float4 copy, 4096 floats
        {
            const float4* src = (const float4*)(WT + kt * HH);
            float4* dst = (float4*)Ws;
#pragma unroll
            for (int i = 0; i < 4; i++) dst[t + i * 256] = src[t + i * 256];
        }
        // X tile: coalesced float4 loads, transposed scatter into Xs[k][row]
        {
#pragma unroll
            for (int i = 0; i < 2; i++) {
                int idx = t + i * 256;      // 0..511
                int row = idx >> 3;         // 0..63
                int c4 = idx & 7;           // float4 within 32 cols
                int gm = m0 + row;
                float4 xv = make_float4(0.f, 0.f, 0.f, 0.f);
                if (gm < M) xv = ((const float4*)X)[gm * (HH / 4) + (kt >> 2) + c4];
                int kk = c4 * 4;
                Xs[(kk + 0) * XS_STRIDE + row] = xv.x;
                Xs[(kk + 1) * XS_STRIDE + row] = xv.y;
                Xs[(kk + 2) * XS_STRIDE + row] = xv.z;
                Xs[(kk + 3) * XS_STRIDE + row] = xv.w;
            }
        }
        __syncthreads();

#pragma unroll
        for (int kk = 0; kk < BK; kk++) {
            float4 w4 = *(const float4*)(Ws + kk * HH + c0);
            unsigned long long b0 = pack2(w4.x, w4.x);
            unsigned long long b1 = pack2(w4.y, w4.y);
            unsigned long long b2 = pack2(w4.z, w4.z);
            unsigned long long b3 = pack2(w4.w, w4.w);
            const float* xp = Xs + kk * XS_STRIDE + r0;
            ulonglong2 aA = *(const ulonglong2*)(xp);       // rows r0..r0+3
            ulonglong2 aB = *(const ulonglong2*)(xp + 4);   // rows r0+4..r0+7
            unsigned long long a0 = aA.x, a1 = aA.y, a2 = aB.x, a3 = aB.y;
            acc[0][0] = fma2(a0, b0, acc[0][0]);
            acc[0][1] = fma2(a0, b1, acc[0][1]);
            acc[0][2] = fma2(a0, b2, acc[0][2]);
            acc[0][3] = fma2(a0, b3, acc[0][3]);
            acc[1][0] = fma2(a1, b0, acc[1][0]);
            acc[1][1] = fma2(a1, b1, acc[1][1]);
            acc[1][2] = fma2(a1, b2, acc[1][2]);
            acc[1][3] = fma2(a1, b3, acc[1][3]);
            acc[2][0] = fma2(a2, b0, acc[2][0]);
            acc[2][1] = fma2(a2, b1, acc[2][1]);
            acc[2][2] = fma2(a2, b2, acc[2][2]);
            acc[2][3] = fma2(a2, b3, acc[2][3]);
            acc[3][0] = fma2(a3, b0, acc[3][0]);
            acc[3][1] = fma2(a3, b1, acc[3][1]);
            acc[3][2] = fma2(a3, b2, acc[3][2]);
            acc[3][3] = fma2(a3, b3, acc[3][3]);
        }
    }

    float4 bias = *(const float4*)(B + c0);
#pragma unroll
    for (int p = 0; p < 4; p++) {
        float2 v0 = unpack2(acc[p][0]);
        float2 v1 = unpack2(acc[p][1]);
        float2 v2 = unpack2(acc[p][2]);
        float2 v3 = unpack2(acc[p][3]);
        int gm = m0 + r0 + 2 * p;
        if (gm < M) {
            float4 o0 = make_float4(v0.x + bias.x, v1.x + bias.y,
                                    v2.x + bias.z, v3.x + bias.w);
            *(float4*)(Y + (size_t)gm * HH + c0) = o0;
        }
        if (gm + 1 < M) {
            float4 o1 = make_float4(v0.y + bias.x, v1.y + bias.y,
                                    v2.y + bias.z, v3.y + bias.w);
            *(float4*)(Y + (size_t)(gm + 1) * HH + c0) = o1;
        }
    }
}

// ---------------- K3: warp-per-node attention (fused softmax) ----------------
// lane l owns dims [4l, 4l+4); head of lane = l>>2 (D=16 => 4 lanes/head).
// ctx[i] = (sum_e ex_e * V_e) / (sum_e ex_e)  -- division deferred.
__global__ void __launch_bounds__(256) attn_kernel(const int* __restrict__ ki,
                                                   float* __restrict__ out,
                                                   int n) {
    int warp = (blockIdx.x * blockDim.x + threadIdx.x) >> 5;
    int lane = threadIdx.x & 31;
    if (warp >= n) return;
    int i = warp;
    const float* Qn = g_P[0];
    const float* Kn = g_P[1];
    const float* Vn = g_P[2];

    float4 qv = ((const float4*)(Qn + (size_t)i * HH))[lane];
    int beg = g_off[i];
    int end = g_off[i + 1];

    float4 acc = make_float4(0.f, 0.f, 0.f, 0.f);
    float den = 0.f;

    int kn_next = 0;
    if (beg < end) kn_next = ki[g_eid[beg]];

    for (int j = beg; j < end; j++) {
        int kn = kn_next;
        if (j + 1 < end) kn_next = ki[g_eid[j + 1]];
        float4 k4 = ((const float4*)(Kn + (size_t)kn * HH))[lane];
        float4 v4 = ((const float4*)(Vn + (size_t)kn * HH))[lane];
        float s = qv.x * k4.x + qv.y * k4.y + qv.z * k4.z + qv.w * k4.w;
        s += __shfl_xor_sync(0xffffffffu, s, 1);
        s += __shfl_xor_sync(0xffffffffu, s, 2);   // per-head dot over 16 dims
        float ex = __expf(s * 0.25f);               // / sqrt(D), D=16
        den += ex;
        acc.x += ex * v4.x;
        acc.y += ex * v4.y;
        acc.z += ex * v4.z;
        acc.w += ex * v4.w;
    }

    float inv = (end > beg) ? (1.f / den) : 0.f;
    float4 o = make_float4(acc.x * inv, acc.y * inv, acc.z * inv, acc.w * inv);
    ((float4*)(out + (size_t)i * HH))[lane] = o;
}

// ---------------- launch ----------------
extern "C" void kernel_launch(void* const* d_in, const int* in_sizes, int n_in,
                              void* d_out, int out_size) {
    const float* q = (const float*)d_in[0];
    const float* k = (const float*)d_in[1];
    const float* v = (const float*)d_in[2];
    const float* Wq = (const float*)d_in[3];
    const float* bq = (const float*)d_in[4];
    const float* Wk = (const float*)d_in[5];
    const float* bk = (const float*)d_in[6];
    const float* Wv = (const float*)d_in[7];
    const float* bv = (const float*)d_in[8];
    const int* qi = (const int*)d_in[9];
    const int* ki = (const int*)d_in[10];

    int Nn = in_sizes[0] / HH;   // 50000
    int E = in_sizes[9];         // 800000
    float* out = (float*)d_out;

    // weight transpose (independent of CSR chain, same stream = ordered anyway)
    wt_kernel<<<dim3(64, 3), 256>>>(Wq, Wk, Wv);

    // CSR build over destination nodes
    zero_kernel<<<(Nn + 255) / 256, 256>>>(Nn);
    hist_kernel<<<(E + 255) / 256, 256>>>(qi, E);
    scan_kernel<<<1, 1024>>>(Nn);
    scatter_kernel<<<(E + 255) / 256, 256>>>(qi, E);

    // per-node projections Qn/Kn/Vn
    proj_gemm<<<dim3((Nn + BM - 1) / BM, 1, 3), 256>>>(q, k, v, bq, bk, bv, Nn);

    // fused gather + scores + softmax + aggregate
    int warps = Nn;
    attn_kernel<<<((long long)warps * 32 + 255) / 256, 256>>>(ki, out, Nn);
}